// round 12
// baseline (speedup 1.0000x reference)
#include <cuda_runtime.h>
#include <cuda_fp16.h>
#include <cstdint>

#define HW    1024
#define Ntok  32768
#define Kcode 1024
#define Ddim  256
#define OUT_ELEMS ((size_t)8388608)
#define CAP   64
#define ENC_BYTES ((size_t)Ntok * Kcode * 4)   // 134217728

// static scratch
__device__ __align__(128) __half g_Aext[(size_t)Ntok * 512];   // 32 MB [h1|h2]
__device__ __align__(128) __half g_Bg[Kcode * 256];            // g1 digits
__device__ __align__(128) unsigned short g_cand[(size_t)Ntok * CAP];  // 4 MB
__device__ unsigned int g_bmax[Ntok];     // running coarse max (ordered bits)
__device__ int    g_ccnt[Ntok];
__device__ float  g_wn2[Kcode];
__device__ float  g_xn[Ntok];
__device__ int    g_gn2max;
__device__ int    g_counts[Kcode];
__device__ double g_xsum, g_bsum;

// ---------------- PTX helpers ----------------
__device__ __forceinline__ uint32_t smem_u32(const void* p) {
    uint32_t a;
    asm("{ .reg .u64 t; cvta.to.shared.u64 t, %1; cvt.u32.u64 %0, t; }" : "=r"(a) : "l"(p));
    return a;
}
#define CP_ASYNC16(dst, src) \
    asm volatile("cp.async.cg.shared.global [%0], [%1], 16;" :: "r"(dst), "l"(src) : "memory")
#define CP_COMMIT() asm volatile("cp.async.commit_group;" ::: "memory")
#define CP_WAIT1()  asm volatile("cp.async.wait_group 1;" ::: "memory")

#define LDMATRIX_X4(r0, r1, r2, r3, addr) \
    asm volatile("ldmatrix.sync.aligned.m8n8.x4.shared.b16 {%0,%1,%2,%3}, [%4];" \
        : "=r"(r0), "=r"(r1), "=r"(r2), "=r"(r3) : "r"(addr))

#define MMA16816(c0, c1, c2, c3, a0, a1, a2, a3, b0, b1) \
    asm volatile("mma.sync.aligned.m16n8k16.row.col.f32.f16.f16.f32 " \
        "{%0,%1,%2,%3}, {%4,%5,%6,%7}, {%8,%9}, {%0,%1,%2,%3};" \
        : "+f"(c0), "+f"(c1), "+f"(c2), "+f"(c3) \
        : "r"(a0), "r"(a1), "r"(a2), "r"(a3), "r"(b0), "r"(b1))

// ---------------- zero / idempotency (+ enc head/tail 8B) ----------------
__global__ void zero_kernel(float* __restrict__ enc) {
    const int i = blockIdx.x * 1024 + threadIdx.x;   // 32 x 1024
    if (i < Ntok)  { g_bmax[i] = 0u; g_ccnt[i] = 0; }
    if (i < Kcode) g_counts[i] = 0;
    if (i == 0) {
        g_xsum = 0.0; g_bsum = 0.0; g_gn2max = 0;
        enc[0] = 0.f; enc[1] = 0.f;                                  // head 8B
        enc[Ntok * (size_t)Kcode - 2] = 0.f;
        enc[Ntok * (size_t)Kcode - 1] = 0.f;                         // tail 8B
    }
}

// ---------------- merged conv: [0,1024) codes, [1024,2048) token tiles ----------------
__global__ void __launch_bounds__(256) conv_kernel(const float* __restrict__ weight,
                                                   const float* __restrict__ input) {
    const int tid = threadIdx.x;
    if (blockIdx.x < 1024) {
        __shared__ float red[256];
        const int k = blockIdx.x;
        const float x = weight[(size_t)k * Ddim + tid];
        g_Bg[(size_t)k * 256 + tid] = __float2half_rn(x);
        red[tid] = x * x;
        __syncthreads();
        for (int o = 128; o > 0; o >>= 1) {
            if (tid < o) red[tid] += red[tid + o];
            __syncthreads();
        }
        if (tid == 0) {
            g_wn2[k] = red[0];
            atomicMax(&g_gn2max, __float_as_int(red[0]));
        }
    } else {
        __shared__ __half h[2][32][264];
        __shared__ float xpart[8][33];
        const int lane = tid & 31, dg = tid >> 5;
        const int n0 = (blockIdx.x - 1024) * 32;
        const int b = n0 / HW, hw0 = n0 % HW;
        const float* ib = input + (size_t)b * Ddim * HW + hw0;
        float xs = 0.f;
        for (int d = dg; d < Ddim; d += 8) {
            float x = ib[(size_t)d * HW + lane];
            xs += x * x;
            __half h1 = __float2half_rn(x);
            float r1 = x - __half2float(h1);
            h[0][lane][d] = h1;
            h[1][lane][d] = __float2half_rn(r1);
        }
        xpart[dg][lane] = xs;
        __syncthreads();
        if (tid < 32) {
            float tot = 0.f;
            #pragma unroll
            for (int g = 0; g < 8; g++) tot += xpart[g][tid];
            g_xn[n0 + tid] = sqrtf(tot);
            #pragma unroll
            for (int o = 16; o > 0; o >>= 1) tot += __shfl_down_sync(0xffffffffu, tot, o);
            if (tid == 0) atomicAdd(&g_xsum, (double)tot);
        }
        for (int o = tid; o < 32 * 64; o += 256) {
            const int row = o >> 6, s16 = o & 63;
            const int dig = s16 >> 5, dsrc = (s16 & 31) * 8;
            const uint4 v = *(const uint4*)&h[dig][row][dsrc];
            *(uint4*)((char*)g_Aext + (size_t)(n0 + row) * 1024 + s16 * 16) = v;
        }
    }
}

// ---------------- coarse HMMA GEMM (CTA 256x128, warp 64x64) + cand push + enc zero ----
#define STAGE_BYTES 49152
#define SMEM_TOTAL (1024 + 3 * STAGE_BYTES + 512)
#define ENC_Q4     ((ENC_BYTES - 16) / 16)   // 8388607 uint4 in the 16B-aligned middle

__device__ __forceinline__ void fill_stage(uint32_t sb, const char* Aab, const char* Bgb,
                                           int tid, int g) {
    const int slot = g % 3;
    const uint32_t SA = sb + slot * STAGE_BYTES;
    const uint32_t SB = SA + 32768;
    const char* As = Aab + g * 128;
    const char* Bs = Bgb + g * 128;
    #pragma unroll
    for (int o = 0; o < 8; o++) {                      // A: 256 rows x 8 chunks
        const int idx = tid + o * 256, row = idx >> 3, c16 = idx & 7;
        const uint32_t sw = (uint32_t)(c16 * 16) ^ (uint32_t)((row & 7) * 16);
        CP_ASYNC16(SA + row * 128 + sw, As + (size_t)row * 1024 + c16 * 16);
    }
    #pragma unroll
    for (int o = 0; o < 4; o++) {                      // B: 128 rows x 8 chunks
        const int idx = tid + o * 256, row = idx >> 3, c16 = idx & 7;
        const uint32_t sw = (uint32_t)(c16 * 16) ^ (uint32_t)((row & 7) * 16);
        CP_ASYNC16(SB + row * 128 + sw, Bs + (size_t)row * 512 + c16 * 16);
    }
}

__global__ void __launch_bounds__(256, 1) gemm_kernel(uint4* __restrict__ encq) {
    extern __shared__ char smem[];
    const uint32_t sbr = smem_u32(smem);
    const uint32_t sb = (sbr + 1023) & ~1023u;
    char* smbase = smem + (sb - sbr);
    float* swn = (float*)(smbase + 3 * STAGE_BYTES);

    const int tid = threadIdx.x, warp = tid >> 5, lane = tid & 31;
    const int warp_m = warp & 3;       // 4 M-blocks of 64 rows
    const int warp_n = warp >> 2;      // 2 N-blocks of 64 cols
    const int n0 = blockIdx.x * 256;
    const int cbase = blockIdx.y * 128;
    const char* Aab = (const char*)g_Aext + (size_t)n0 * 1024;
    const char* Bgb = (const char*)g_Bg + (size_t)cbase * 512;

    if (tid < 128) swn[tid] = g_wn2[cbase + tid];

    fill_stage(sb, Aab, Bgb, tid, 0); CP_COMMIT();
    fill_stage(sb, Aab, Bgb, tid, 1); CP_COMMIT();

    float c[4][8][4];
    #pragma unroll
    for (int mt = 0; mt < 4; mt++)
        #pragma unroll
        for (int nt = 0; nt < 8; nt++)
            #pragma unroll
            for (int j = 0; j < 4; j++) c[mt][nt][j] = 0.f;

    const int arowL = (lane & 15);
    const uint32_t aLow = (uint32_t)((lane >> 4) << 4);
    const int browL = ((lane >> 4) & 1) * 8 + (lane & 7);
    const uint32_t bKb = (uint32_t)(((lane >> 3) & 1) * 16);
    const uint32_t bswz = (uint32_t)((lane & 7) * 16);

    // enc zero region: 1024 CTAs x 8192 uint4 (128 KB each)
    const size_t ezBase = (size_t)(blockIdx.y * 128 + blockIdx.x) * 8192;
    const uint4 zq = make_uint4(0u, 0u, 0u, 0u);

    for (int g = 0; g < 4; g++) {
        CP_WAIT1();
        __syncthreads();
        if (g + 2 < 4) fill_stage(sb, Aab, Bgb, tid, g + 2);
        CP_COMMIT();
        // background enc zeroing: 2048 uint4 per stage
        {
            const size_t zb = ezBase + (size_t)g * 2048;
            #pragma unroll
            for (int i = 0; i < 8; i++) {
                const size_t idx = zb + i * 256 + tid;
                if (idx < ENC_Q4) encq[idx] = zq;
            }
        }
        const uint32_t SA = sb + (g % 3) * STAGE_BYTES;
        const uint32_t SB = SA + 32768;
        #pragma unroll
        for (int k16 = 0; k16 < 4; k16++) {
            const uint32_t kOff = (uint32_t)(k16 * 32);
            uint32_t a[4][4];
            #pragma unroll
            for (int mt = 0; mt < 4; mt++) {
                const int arow = warp_m * 64 + mt * 16 + arowL;
                LDMATRIX_X4(a[mt][0], a[mt][1], a[mt][2], a[mt][3],
                            SA + arow * 128 + ((kOff + aLow) ^ (uint32_t)((arow & 7) * 16)));
            }
            #pragma unroll
            for (int np = 0; np < 4; np++) {
                uint32_t b0, b1, b2, b3;
                const uint32_t brow = (uint32_t)(warp_n * 64 + np * 16 + browL);
                LDMATRIX_X4(b0, b1, b2, b3, SB + brow * 128 + ((kOff + bKb) ^ bswz));
                #pragma unroll
                for (int mt = 0; mt < 4; mt++) {
                    MMA16816(c[mt][2 * np][0], c[mt][2 * np][1], c[mt][2 * np][2], c[mt][2 * np][3],
                             a[mt][0], a[mt][1], a[mt][2], a[mt][3], b0, b1);
                    MMA16816(c[mt][2 * np + 1][0], c[mt][2 * np + 1][1],
                             c[mt][2 * np + 1][2], c[mt][2 * np + 1][3],
                             a[mt][0], a[mt][1], a[mt][2], a[mt][3], b2, b3);
                }
            }
        }
    }

    // epilogue: running coarse max + candidate push
    const float gmaxn = sqrtf(__int_as_float(g_gn2max));
    #pragma unroll
    for (int mt = 0; mt < 4; mt++) {
        #pragma unroll
        for (int grp = 0; grp < 2; grp++) {
            const int row = warp_m * 64 + mt * 16 + grp * 8 + (lane >> 2);
            const int token = n0 + row;
            float sv[16];
            float smax = -3.4e38f;
            #pragma unroll
            for (int nt = 0; nt < 8; nt++) {
                const int cc = warp_n * 64 + nt * 8 + (lane & 3) * 2;
                const float s0 = 2.f * c[mt][nt][2 * grp]     - swn[cc];
                const float s1 = 2.f * c[mt][nt][2 * grp + 1] - swn[cc + 1];
                sv[nt * 2] = s0; sv[nt * 2 + 1] = s1;
                smax = fmaxf(smax, fmaxf(s0, s1));
            }
            smax = fmaxf(smax, __shfl_xor_sync(0xffffffffu, smax, 1));
            smax = fmaxf(smax, __shfl_xor_sync(0xffffffffu, smax, 2));
            const uint32_t f = __float_as_uint(smax);
            const uint32_t ord = (f & 0x80000000u) ? ~f : (f | 0x80000000u);
            uint32_t old = 0;
            if ((lane & 3) == 0) old = atomicMax(&g_bmax[token], ord);
            old = __shfl_sync(0xffffffffu, old, lane & ~3);
            const uint32_t cur = old > ord ? old : ord;
            const float curF = (cur & 0x80000000u) ? __uint_as_float(cur & 0x7FFFFFFFu)
                                                   : __uint_as_float(~cur);
            const float thr = curF - (g_xn[token] * gmaxn * (1.f / 256.f) + 0.25f);
            #pragma unroll
            for (int q = 0; q < 16; q++) {
                if (sv[q] >= thr) {
                    const int code = cbase + warp_n * 64 + (q >> 1) * 8 + (lane & 3) * 2 + (q & 1);
                    const int slot = atomicAdd(&g_ccnt[token], 1);
                    if (slot < CAP) g_cand[(size_t)token * CAP + slot] = (unsigned short)code;
                }
            }
        }
    }
}

// ---------------- fused tail: exact refine from candidates + one-hot + out ----------------
__global__ void __launch_bounds__(1024) tail_kernel(const float* __restrict__ weight,
                                                    float* __restrict__ enc,
                                                    float* __restrict__ out) {
    const int tid = threadIdx.x, lane = tid & 31, warp = tid >> 5;
    const int t0 = blockIdx.x * 32;
    const int t = t0 + warp;
    __shared__ int six[32];
    __shared__ double bsh[32];
    __shared__ float q[32][257];

    // reconstruct x from digits (err ~2^-22)
    float xr[8];
    {
        const __half* xa = g_Aext + (size_t)t * 512 + lane * 8;
        uint4 v1 = *(const uint4*)xa;
        uint4 v2 = *(const uint4*)(xa + 256);
        const uint32_t* u1 = (const uint32_t*)&v1;
        const uint32_t* u2 = (const uint32_t*)&v2;
        #pragma unroll
        for (int qq = 0; qq < 4; qq++) {
            float2 a = __half22float2(*(const __half2*)&u1[qq]);
            float2 b = __half22float2(*(const __half2*)&u2[qq]);
            xr[qq * 2]     = a.x + b.x;
            xr[qq * 2 + 1] = a.y + b.y;
        }
    }

    const int cnt = g_ccnt[t];
    float bestE = -3.4e38f; int bidx = 0x7FFFFFFF;

    if (cnt <= CAP) {
        for (int i = 0; i < cnt; i++) {
            const int code = g_cand[(size_t)t * CAP + i];
            const float4* w4 = (const float4*)(weight + (size_t)code * Ddim) + lane * 2;
            const float4 a = w4[0], b = w4[1];
            float d = xr[0] * a.x;
            d = fmaf(xr[1], a.y, d); d = fmaf(xr[2], a.z, d); d = fmaf(xr[3], a.w, d);
            d = fmaf(xr[4], b.x, d); d = fmaf(xr[5], b.y, d);
            d = fmaf(xr[6], b.z, d); d = fmaf(xr[7], b.w, d);
            #pragma unroll
            for (int x = 16; x > 0; x >>= 1) d += __shfl_xor_sync(0xffffffffu, d, x);
            const float s = 2.f * d - g_wn2[code];
            if (s > bestE || (s == bestE && code < bidx)) { bestE = s; bidx = code; }
        }
    } else {
        for (int code = 0; code < Kcode; code++) {
            const float4* w4 = (const float4*)(weight + (size_t)code * Ddim) + lane * 2;
            const float4 a = w4[0], b = w4[1];
            float d = xr[0] * a.x;
            d = fmaf(xr[1], a.y, d); d = fmaf(xr[2], a.z, d); d = fmaf(xr[3], a.w, d);
            d = fmaf(xr[4], b.x, d); d = fmaf(xr[5], b.y, d);
            d = fmaf(xr[6], b.z, d); d = fmaf(xr[7], b.w, d);
            #pragma unroll
            for (int x = 16; x > 0; x >>= 1) d += __shfl_xor_sync(0xffffffffu, d, x);
            const float s = 2.f * d - g_wn2[code];
            if (s > bestE || (s == bestE && code < bidx)) { bestE = s; bidx = code; }
        }
    }

    if (lane == 0) {
        six[warp] = bidx;
        bsh[warp] = (double)bestE;
        atomicAdd(&g_counts[bidx], 1);
        enc[(size_t)t * Kcode + bidx] = 1.0f;   // rows pre-zeroed by gemm_kernel
    }

    __syncthreads();
    if (tid == 0) {
        double s = 0.0;
        #pragma unroll
        for (int w8 = 0; w8 < 32; w8++) s += bsh[w8];
        atomicAdd(&g_bsum, s);
    }

    // gather codebook rows -> out (BCHW)
    for (int e4 = tid; e4 < 32 * 64; e4 += 1024) {
        const int tt = e4 >> 6, d4 = (e4 & 63) * 4;
        float4 v = *(const float4*)&weight[(size_t)six[tt] * Ddim + d4];
        q[tt][d4] = v.x; q[tt][d4 + 1] = v.y; q[tt][d4 + 2] = v.z; q[tt][d4 + 3] = v.w;
    }
    __syncthreads();
    const int b = t0 / HW, hw0 = t0 % HW;
    float* ob = out + (size_t)b * Ddim * HW;
    #pragma unroll 4
    for (int ch = warp; ch < Ddim; ch += 32)
        ob[(size_t)ch * HW + hw0 + lane] = q[lane][ch];
}

__global__ void finalize_kernel(float* __restrict__ outLoss, float* __restrict__ outEnt) {
    __shared__ double sh[256];
    const int tid = threadIdx.x;
    double s = 0.0;
    for (int k = tid; k < Kcode; k += 256) {
        const float p = (float)g_counts[k] * (1.0f / (float)Ntok);
        s += (double)(p * logf(p + 1e-10f));
    }
    sh[tid] = s; __syncthreads();
    for (int o = 128; o > 0; o >>= 1) { if (tid < o) sh[tid] += sh[tid + o]; __syncthreads(); }
    if (tid == 0) {
        outEnt[0]  = (float)(-sh[0]);
        outLoss[0] = (float)(0.25 * (g_xsum - g_bsum) / (double)((size_t)Ntok * Ddim));
    }
}

// ---------------- launch ----------------
extern "C" void kernel_launch(void* const* d_in, const int* in_sizes, int n_in,
                              void* d_out, int out_size) {
    const float* input  = (const float*)d_in[0];
    const float* weight = (const float*)d_in[1];
    float* out     = (float*)d_out;
    float* outLoss = out + OUT_ELEMS;
    float* outEnt  = outLoss + 1;
    float* enc     = outEnt + 1;

    static int attr_done = 0;
    if (!attr_done) {
        cudaFuncSetAttribute(gemm_kernel, cudaFuncAttributeMaxDynamicSharedMemorySize, SMEM_TOTAL);
        attr_done = 1;
    }

    zero_kernel<<<32, 1024>>>(enc);
    conv_kernel<<<2048, 256>>>(weight, input);
    gemm_kernel<<<dim3(128, 8), 256, SMEM_TOTAL>>>((uint4*)((char*)enc + 8));
    tail_kernel<<<Ntok / 32, 1024>>>(weight, enc, out);
    finalize_kernel<<<1, 256>>>(outLoss, outEnt);
}

// round 13
// speedup vs baseline: 1.2056x; 1.2056x over previous
#include <cuda_runtime.h>
#include <cuda_fp16.h>
#include <cstdint>

#define HW    1024
#define Ntok  32768
#define Kcode 1024
#define Ddim  256
#define OUT_ELEMS ((size_t)8388608)
#define CAP   64
#define ENC_BYTES ((size_t)Ntok * Kcode * 4)   // 134217728
#define ENC_Q4    ((ENC_BYTES - 16) / 16)      // uint4 count in 16B-aligned middle

// static scratch
__device__ __align__(128) __half g_Aext[(size_t)Ntok * 512];   // 32 MB [h1|h2]
__device__ __align__(128) __half g_Bg[Kcode * 256];            // g1 digits
__device__ __align__(128) unsigned short g_cand[(size_t)Ntok * CAP];  // 4 MB
__device__ unsigned int g_bmax[Ntok];     // running coarse max (ordered bits)
__device__ int    g_ccnt[Ntok];
__device__ float  g_wn2[Kcode];
__device__ float  g_xn[Ntok];
__device__ int    g_gn2max;
__device__ int    g_counts[Kcode];
__device__ double g_xsum, g_bsum;

// ---------------- PTX helpers ----------------
__device__ __forceinline__ uint32_t smem_u32(const void* p) {
    uint32_t a;
    asm("{ .reg .u64 t; cvta.to.shared.u64 t, %1; cvt.u32.u64 %0, t; }" : "=r"(a) : "l"(p));
    return a;
}
#define CP_ASYNC16(dst, src) \
    asm volatile("cp.async.cg.shared.global [%0], [%1], 16;" :: "r"(dst), "l"(src) : "memory")
#define CP_COMMIT() asm volatile("cp.async.commit_group;" ::: "memory")
#define CP_WAIT1()  asm volatile("cp.async.wait_group 1;" ::: "memory")

#define LDMATRIX_X4(r0, r1, r2, r3, addr) \
    asm volatile("ldmatrix.sync.aligned.m8n8.x4.shared.b16 {%0,%1,%2,%3}, [%4];" \
        : "=r"(r0), "=r"(r1), "=r"(r2), "=r"(r3) : "r"(addr))

#define MMA16816(c0, c1, c2, c3, a0, a1, a2, a3, b0, b1) \
    asm volatile("mma.sync.aligned.m16n8k16.row.col.f32.f16.f16.f32 " \
        "{%0,%1,%2,%3}, {%4,%5,%6,%7}, {%8,%9}, {%0,%1,%2,%3};" \
        : "+f"(c0), "+f"(c1), "+f"(c2), "+f"(c3) \
        : "r"(a0), "r"(a1), "r"(a2), "r"(a3), "r"(b0), "r"(b1))

// ---------------- zero / idempotency (+ enc head/tail 8B) ----------------
__global__ void zero_kernel(float* __restrict__ enc) {
    const int i = blockIdx.x * 1024 + threadIdx.x;   // 32 x 1024
    if (i < Ntok)  { g_bmax[i] = 0u; g_ccnt[i] = 0; }
    if (i < Kcode) g_counts[i] = 0;
    if (i == 0) {
        g_xsum = 0.0; g_bsum = 0.0; g_gn2max = 0;
        enc[0] = 0.f; enc[1] = 0.f;
        enc[Ntok * (size_t)Kcode - 2] = 0.f;
        enc[Ntok * (size_t)Kcode - 1] = 0.f;
    }
}

// ---------------- merged conv: [0,1024) codes, [1024,2048) token tiles ----------------
__global__ void __launch_bounds__(256) conv_kernel(const float* __restrict__ weight,
                                                   const float* __restrict__ input) {
    const int tid = threadIdx.x;
    if (blockIdx.x < 1024) {
        __shared__ float red[256];
        const int k = blockIdx.x;
        const float x = weight[(size_t)k * Ddim + tid];
        g_Bg[(size_t)k * 256 + tid] = __float2half_rn(x);
        red[tid] = x * x;
        __syncthreads();
        for (int o = 128; o > 0; o >>= 1) {
            if (tid < o) red[tid] += red[tid + o];
            __syncthreads();
        }
        if (tid == 0) {
            g_wn2[k] = red[0];
            atomicMax(&g_gn2max, __float_as_int(red[0]));
        }
    } else {
        __shared__ __half h[2][32][264];
        __shared__ float xpart[8][33];
        const int lane = tid & 31, dg = tid >> 5;
        const int n0 = (blockIdx.x - 1024) * 32;
        const int b = n0 / HW, hw0 = n0 % HW;
        const float* ib = input + (size_t)b * Ddim * HW + hw0;
        float xs = 0.f;
        for (int d = dg; d < Ddim; d += 8) {
            float x = ib[(size_t)d * HW + lane];
            xs += x * x;
            __half h1 = __float2half_rn(x);
            float r1 = x - __half2float(h1);
            h[0][lane][d] = h1;
            h[1][lane][d] = __float2half_rn(r1);
        }
        xpart[dg][lane] = xs;
        __syncthreads();
        if (tid < 32) {
            float tot = 0.f;
            #pragma unroll
            for (int g = 0; g < 8; g++) tot += xpart[g][tid];
            g_xn[n0 + tid] = sqrtf(tot);
            #pragma unroll
            for (int o = 16; o > 0; o >>= 1) tot += __shfl_down_sync(0xffffffffu, tot, o);
            if (tid == 0) atomicAdd(&g_xsum, (double)tot);
        }
        for (int o = tid; o < 32 * 64; o += 256) {
            const int row = o >> 6, s16 = o & 63;
            const int dig = s16 >> 5, dsrc = (s16 & 31) * 8;
            const uint4 v = *(const uint4*)&h[dig][row][dsrc];
            *(uint4*)((char*)g_Aext + (size_t)(n0 + row) * 1024 + s16 * 16) = v;
        }
    }
}

// ---------------- coarse HMMA GEMM (CTA 128x128, warp 32x64) + cand push + enc zero ----
#define SMEM_TOTAL (1024 + 3 * 32768 + 512)

__device__ __forceinline__ void fill_stage(uint32_t sb, const char* Aab, const char* Bgb,
                                           int tid, int g) {
    const int slot = g % 3;
    const uint32_t SA = sb + slot * 32768;
    const uint32_t SB = SA + 16384;
    const char* As = Aab + g * 128;
    const char* Bs = Bgb + g * 128;
    #pragma unroll
    for (int o = 0; o < 4; o++) {
        const int idx = tid + o * 256, row = idx >> 3, c16 = idx & 7;
        const uint32_t sw = (uint32_t)(c16 * 16) ^ (uint32_t)((row & 7) * 16);
        CP_ASYNC16(SA + row * 128 + sw, As + (size_t)row * 1024 + c16 * 16);
        CP_ASYNC16(SB + row * 128 + sw, Bs + (size_t)row * 512  + c16 * 16);
    }
}

__global__ void __launch_bounds__(256, 2) gemm_kernel(uint4* __restrict__ encq) {
    extern __shared__ char smem[];
    const uint32_t sbr = smem_u32(smem);
    const uint32_t sb = (sbr + 1023) & ~1023u;
    char* smbase = smem + (sb - sbr);
    float* swn = (float*)(smbase + 3 * 32768);

    const int tid = threadIdx.x, warp = tid >> 5, lane = tid & 31;
    const int warp_m = warp & 3;       // 4 M-blocks of 32 rows
    const int warp_n = warp >> 2;      // 2 N-blocks of 64 cols
    const int n0 = blockIdx.x * 128;
    const int cbase = blockIdx.y * 128;
    const char* Aab = (const char*)g_Aext + (size_t)n0 * 1024;
    const char* Bgb = (const char*)g_Bg + (size_t)cbase * 512;

    if (tid < 128) swn[tid] = g_wn2[cbase + tid];

    fill_stage(sb, Aab, Bgb, tid, 0); CP_COMMIT();
    fill_stage(sb, Aab, Bgb, tid, 1); CP_COMMIT();

    float c[2][8][4];
    #pragma unroll
    for (int mt = 0; mt < 2; mt++)
        #pragma unroll
        for (int nt = 0; nt < 8; nt++)
            #pragma unroll
            for (int j = 0; j < 4; j++) c[mt][nt][j] = 0.f;

    const int arowL = (lane & 15);
    const uint32_t aLow = (uint32_t)((lane >> 4) << 4);
    const int browL = ((lane >> 4) & 1) * 8 + (lane & 7);
    const uint32_t bKb = (uint32_t)(((lane >> 3) & 1) * 16);
    const uint32_t bswz = (uint32_t)((lane & 7) * 16);

    // enc zero region: 2048 CTAs x 4096 uint4 (64 KB each)
    const size_t ezBase = (size_t)(blockIdx.y * 256 + blockIdx.x) * 4096;
    const uint4 zq = make_uint4(0u, 0u, 0u, 0u);

    for (int g = 0; g < 4; g++) {
        CP_WAIT1();
        __syncthreads();
        if (g + 2 < 4) fill_stage(sb, Aab, Bgb, tid, g + 2);
        CP_COMMIT();
        // background enc zeroing: 1024 uint4 per stage (hidden under MMA)
        {
            const size_t zb = ezBase + (size_t)g * 1024;
            #pragma unroll
            for (int i = 0; i < 4; i++) {
                const size_t idx = zb + i * 256 + tid;
                if (idx < ENC_Q4) encq[idx] = zq;
            }
        }
        const uint32_t SA = sb + (g % 3) * 32768;
        const uint32_t SB = SA + 16384;
        #pragma unroll
        for (int k16 = 0; k16 < 4; k16++) {
            const uint32_t kOff = (uint32_t)(k16 * 32);
            uint32_t a[2][4];
            #pragma unroll
            for (int mt = 0; mt < 2; mt++) {
                const int arow = warp_m * 32 + mt * 16 + arowL;
                LDMATRIX_X4(a[mt][0], a[mt][1], a[mt][2], a[mt][3],
                            SA + arow * 128 + ((kOff + aLow) ^ (uint32_t)((arow & 7) * 16)));
            }
            #pragma unroll
            for (int np = 0; np < 4; np++) {
                uint32_t b0, b1, b2, b3;
                const uint32_t brow = (uint32_t)(warp_n * 64 + np * 16 + browL);
                LDMATRIX_X4(b0, b1, b2, b3, SB + brow * 128 + ((kOff + bKb) ^ bswz));
                #pragma unroll
                for (int mt = 0; mt < 2; mt++) {
                    MMA16816(c[mt][2 * np][0], c[mt][2 * np][1], c[mt][2 * np][2], c[mt][2 * np][3],
                             a[mt][0], a[mt][1], a[mt][2], a[mt][3], b0, b1);
                    MMA16816(c[mt][2 * np + 1][0], c[mt][2 * np + 1][1],
                             c[mt][2 * np + 1][2], c[mt][2 * np + 1][3],
                             a[mt][0], a[mt][1], a[mt][2], a[mt][3], b2, b3);
                }
            }
        }
    }

    // epilogue: running coarse max + candidate push
    const float gmaxn = sqrtf(__int_as_float(g_gn2max));
    #pragma unroll
    for (int mt = 0; mt < 2; mt++) {
        #pragma unroll
        for (int grp = 0; grp < 2; grp++) {
            const int row = warp_m * 32 + mt * 16 + grp * 8 + (lane >> 2);
            const int token = n0 + row;
            float sv[16];
            float smax = -3.4e38f;
            #pragma unroll
            for (int nt = 0; nt < 8; nt++) {
                const int cc = warp_n * 64 + nt * 8 + (lane & 3) * 2;
                const float s0 = 2.f * c[mt][nt][2 * grp]     - swn[cc];
                const float s1 = 2.f * c[mt][nt][2 * grp + 1] - swn[cc + 1];
                sv[nt * 2] = s0; sv[nt * 2 + 1] = s1;
                smax = fmaxf(smax, fmaxf(s0, s1));
            }
            smax = fmaxf(smax, __shfl_xor_sync(0xffffffffu, smax, 1));
            smax = fmaxf(smax, __shfl_xor_sync(0xffffffffu, smax, 2));
            const uint32_t f = __float_as_uint(smax);
            const uint32_t ord = (f & 0x80000000u) ? ~f : (f | 0x80000000u);
            uint32_t old = 0;
            if ((lane & 3) == 0) old = atomicMax(&g_bmax[token], ord);
            old = __shfl_sync(0xffffffffu, old, lane & ~3);
            const uint32_t cur = old > ord ? old : ord;
            const float curF = (cur & 0x80000000u) ? __uint_as_float(cur & 0x7FFFFFFFu)
                                                   : __uint_as_float(~cur);
            const float thr = curF - (g_xn[token] * gmaxn * (1.f / 256.f) + 0.25f);
            #pragma unroll
            for (int q = 0; q < 16; q++) {
                if (sv[q] >= thr) {
                    const int code = cbase + warp_n * 64 + (q >> 1) * 8 + (lane & 3) * 2 + (q & 1);
                    const int slot = atomicAdd(&g_ccnt[token], 1);
                    if (slot < CAP) g_cand[(size_t)token * CAP + slot] = (unsigned short)code;
                }
            }
        }
    }
}

// ---------------- fused tail: exact refine (2-way ILP) + one-hot + out ----------------
__device__ __forceinline__ float cand_dot(const float* __restrict__ weight,
                                          const float* xr, int code, int lane) {
    const float4* w4 = (const float4*)(weight + (size_t)code * Ddim) + lane * 2;
    const float4 a = w4[0], b = w4[1];
    float d = xr[0] * a.x;
    d = fmaf(xr[1], a.y, d); d = fmaf(xr[2], a.z, d); d = fmaf(xr[3], a.w, d);
    d = fmaf(xr[4], b.x, d); d = fmaf(xr[5], b.y, d);
    d = fmaf(xr[6], b.z, d); d = fmaf(xr[7], b.w, d);
    return d;
}

__global__ void __launch_bounds__(1024) tail_kernel(const float* __restrict__ weight,
                                                    float* __restrict__ enc,
                                                    float* __restrict__ out) {
    const int tid = threadIdx.x, lane = tid & 31, warp = tid >> 5;
    const int t0 = blockIdx.x * 32;
    const int t = t0 + warp;
    __shared__ int six[32];
    __shared__ double bsh[32];
    __shared__ float q[32][257];

    // reconstruct x from digits (err ~2^-22)
    float xr[8];
    {
        const __half* xa = g_Aext + (size_t)t * 512 + lane * 8;
        uint4 v1 = *(const uint4*)xa;
        uint4 v2 = *(const uint4*)(xa + 256);
        const uint32_t* u1 = (const uint32_t*)&v1;
        const uint32_t* u2 = (const uint32_t*)&v2;
        #pragma unroll
        for (int qq = 0; qq < 4; qq++) {
            float2 a = __half22float2(*(const __half2*)&u1[qq]);
            float2 b = __half22float2(*(const __half2*)&u2[qq]);
            xr[qq * 2]     = a.x + b.x;
            xr[qq * 2 + 1] = a.y + b.y;
        }
    }

    const int cnt = g_ccnt[t];
    float bestE = -3.4e38f; int bidx = 0x7FFFFFFF;

    if (cnt <= CAP) {
        int i = 0;
        for (; i + 2 <= cnt; i += 2) {
            const int c0 = g_cand[(size_t)t * CAP + i];
            const int c1 = g_cand[(size_t)t * CAP + i + 1];
            float d0 = cand_dot(weight, xr, c0, lane);
            float d1 = cand_dot(weight, xr, c1, lane);
            #pragma unroll
            for (int x = 16; x > 0; x >>= 1) {
                d0 += __shfl_xor_sync(0xffffffffu, d0, x);
                d1 += __shfl_xor_sync(0xffffffffu, d1, x);
            }
            const float s0 = 2.f * d0 - g_wn2[c0];
            const float s1 = 2.f * d1 - g_wn2[c1];
            if (s0 > bestE || (s0 == bestE && c0 < bidx)) { bestE = s0; bidx = c0; }
            if (s1 > bestE || (s1 == bestE && c1 < bidx)) { bestE = s1; bidx = c1; }
        }
        if (i < cnt) {
            const int c0 = g_cand[(size_t)t * CAP + i];
            float d0 = cand_dot(weight, xr, c0, lane);
            #pragma unroll
            for (int x = 16; x > 0; x >>= 1) d0 += __shfl_xor_sync(0xffffffffu, d0, x);
            const float s0 = 2.f * d0 - g_wn2[c0];
            if (s0 > bestE || (s0 == bestE && c0 < bidx)) { bestE = s0; bidx = c0; }
        }
    } else {
        // overflow fallback: exact scan over all codes (correct, ~never taken)
        for (int code = 0; code < Kcode; code += 2) {
            float d0 = cand_dot(weight, xr, code, lane);
            float d1 = cand_dot(weight, xr, code + 1, lane);
            #pragma unroll
            for (int x = 16; x > 0; x >>= 1) {
                d0 += __shfl_xor_sync(0xffffffffu, d0, x);
                d1 += __shfl_xor_sync(0xffffffffu, d1, x);
            }
            const float s0 = 2.f * d0 - g_wn2[code];
            const float s1 = 2.f * d1 - g_wn2[code + 1];
            if (s0 > bestE || (s0 == bestE && code < bidx))       { bestE = s0; bidx = code; }
            if (s1 > bestE || (s1 == bestE && code + 1 < bidx))   { bestE = s1; bidx = code + 1; }
        }
    }

    if (lane == 0) {
        six[warp] = bidx;
        bsh[warp] = (double)bestE;
        atomicAdd(&g_counts[bidx], 1);
        enc[(size_t)t * Kcode + bidx] = 1.0f;   // rows pre-zeroed by gemm_kernel
    }

    __syncthreads();
    if (tid == 0) {
        double s = 0.0;
        #pragma unroll
        for (int w8 = 0; w8 < 32; w8++) s += bsh[w8];
        atomicAdd(&g_bsum, s);
    }

    // gather codebook rows -> out (BCHW)
    for (int e4 = tid; e4 < 32 * 64; e4 += 1024) {
        const int tt = e4 >> 6, d4 = (e4 & 63) * 4;
        float4 v = *(const float4*)&weight[(size_t)six[tt] * Ddim + d4];
        q[tt][d4] = v.x; q[tt][d4 + 1] = v.y; q[tt][d4 + 2] = v.z; q[tt][d4 + 3] = v.w;
    }
    __syncthreads();
    const int b = t0 / HW, hw0 = t0 % HW;
    float* ob = out + (size_t)b * Ddim * HW;
    #pragma unroll 4
    for (int ch = warp; ch < Ddim; ch += 32)
        ob[(size_t)ch * HW + hw0 + lane] = q[lane][ch];
}

__global__ void finalize_kernel(float* __restrict__ outLoss, float* __restrict__ outEnt) {
    __shared__ double sh[256];
    const int tid = threadIdx.x;
    double s = 0.0;
    for (int k = tid; k < Kcode; k += 256) {
        const float p = (float)g_counts[k] * (1.0f / (float)Ntok);
        s += (double)(p * logf(p + 1e-10f));
    }
    sh[tid] = s; __syncthreads();
    for (int o = 128; o > 0; o >>= 1) { if (tid < o) sh[tid] += sh[tid + o]; __syncthreads(); }
    if (tid == 0) {
        outEnt[0]  = (float)(-sh[0]);
        outLoss[0] = (float)(0.25 * (g_xsum - g_bsum) / (double)((size_t)Ntok * Ddim));
    }
}

// ---------------- launch ----------------
extern "C" void kernel_launch(void* const* d_in, const int* in_sizes, int n_in,
                              void* d_out, int out_size) {
    const float* input  = (const float*)d_in[0];
    const float* weight = (const float*)d_in[1];
    float* out     = (float*)d_out;
    float* outLoss = out + OUT_ELEMS;
    float* outEnt  = outLoss + 1;
    float* enc     = outEnt + 1;

    static int attr_done = 0;
    if (!attr_done) {
        cudaFuncSetAttribute(gemm_kernel, cudaFuncAttributeMaxDynamicSharedMemorySize, SMEM_TOTAL);
        attr_done = 1;
    }

    zero_kernel<<<32, 1024>>>(enc);
    conv_kernel<<<2048, 256>>>(weight, input);
    gemm_kernel<<<dim3(256, 8), 256, SMEM_TOTAL>>>((uint4*)((char*)enc + 8));
    tail_kernel<<<Ntok / 32, 1024>>>(weight, enc, out);
    finalize_kernel<<<1, 256>>>(outLoss, outEnt);
}